// round 1
// baseline (speedup 1.0000x reference)
#include <cuda_runtime.h>

#define N_NODES 8192
#define F_DIM 128
#define ALPHA 0.3f
#define MAXDEG 512

// ---- device scratch (no allocations allowed) ----
__device__ float g_v[4 * F_DIM];                   // v1[h0],v1[h1],v2[h0],v2[h1]
__device__ float g_Sx[F_DIM];                      // column sums of x
__device__ float g_sa1[2 * N_NODES];               // [h][n]
__device__ float g_sa2[2 * N_NODES];               // [h][n]
__device__ float g_G[(size_t)N_NODES * 256];       // per-row [g_h0(128) | g_h1(128)]

// ============================================================
// Kernel 1: v1[h] = Wmap[h] @ a1_w[h], v2[h] = Wmap[h] @ a2_w[h]; zero Sx
// ============================================================
__global__ void prep_kernel(const float* __restrict__ Wmap,
                            const float* __restrict__ a1w,
                            const float* __restrict__ a2w) {
    int t = threadIdx.x;          // 0..255 -> (h,f)
    int h = t >> 7, f = t & 127;
    const float* wrow = Wmap + (size_t)(h * F_DIM + f) * 128;
    float s1 = 0.f, s2 = 0.f;
    for (int d = 0; d < 128; ++d) {
        float w = wrow[d];
        s1 = fmaf(w, a1w[h * 128 + d], s1);
        s2 = fmaf(w, a2w[h * 128 + d], s2);
    }
    g_v[h * F_DIM + f] = s1;
    g_v[2 * F_DIM + h * F_DIM + f] = s2;
    if (t < F_DIM) g_Sx[t] = 0.f;
}

// ============================================================
// Kernel 2: column sums of x  (Sx[d] = sum_n x[n,d])
// ============================================================
__global__ void colsum_kernel(const float* __restrict__ x) {
    int d = threadIdx.x;                 // 128 threads
    int r0 = blockIdx.x * 64;            // 128 blocks * 64 rows
    float s = 0.f;
    #pragma unroll 8
    for (int r = 0; r < 64; ++r)
        s += x[(size_t)(r0 + r) * F_DIM + d];
    atomicAdd(&g_Sx[d], s);
}

// ============================================================
// Kernel 3: per-node scores  sa1[h,n], sa2[h,n]
// ============================================================
__global__ void score_kernel(const float* __restrict__ x,
                             const float* __restrict__ a1b,
                             const float* __restrict__ a2b) {
    __shared__ float sv[4 * 128];
    int tid = threadIdx.x;               // 256
    sv[tid] = g_v[tid];
    sv[256 + tid] = g_v[256 + tid];
    __syncthreads();

    int warp = tid >> 5, lane = tid & 31;
    int n = blockIdx.x * 8 + warp;
    const float* xr = x + (size_t)n * F_DIM;
    float x0 = xr[lane], x1 = xr[lane + 32], x2 = xr[lane + 64], x3 = xr[lane + 96];

    float s[4];
    #pragma unroll
    for (int q = 0; q < 4; ++q) {
        const float* v = sv + q * 128;
        float acc = x0 * v[lane] + x1 * v[lane + 32] + x2 * v[lane + 64] + x3 * v[lane + 96];
        #pragma unroll
        for (int o = 16; o > 0; o >>= 1)
            acc += __shfl_down_sync(0xffffffffu, acc, o);
        s[q] = acc;
    }
    if (lane == 0) {
        g_sa1[n]           = s[0] + a1b[0];
        g_sa1[N_NODES + n] = s[1] + a1b[1];
        g_sa2[n]           = s[2] + a2b[0];
        g_sa2[N_NODES + n] = s[3] + a2b[1];
    }
}

// ============================================================
// Kernel 4 (main): per-row adj scan -> sparse softmax -> weighted x gather
//   g_h[i,:] = c_ih*Sx + sum_{j in nbr(i)} beta_ijh * x[j,:]
// ============================================================
__global__ void __launch_bounds__(256) gat_main(const float* __restrict__ adj,
                                                const float* __restrict__ x) {
    __shared__ int   s_list[MAXDEG];
    __shared__ float s_w0[MAXDEG], s_w1[MAXDEG];
    __shared__ int   s_cnt;
    __shared__ float s_red[16];
    __shared__ float s_bc[4];
    __shared__ float s_acc[256];

    int tid = threadIdx.x;
    int i = blockIdx.x;
    if (tid == 0) s_cnt = 0;
    __syncthreads();

    // ---- phase 1: scan adjacency row, collect neighbor indices ----
    const float4* arow = reinterpret_cast<const float4*>(adj + (size_t)i * N_NODES);
    #pragma unroll
    for (int it = 0; it < 8; ++it) {
        int idx = it * 256 + tid;            // 0..2047 float4s
        float4 v = arow[idx];
        int jb = idx << 2;
        if (v.x != 0.f) { int p = atomicAdd(&s_cnt, 1); if (p < MAXDEG) s_list[p] = jb; }
        if (v.y != 0.f) { int p = atomicAdd(&s_cnt, 1); if (p < MAXDEG) s_list[p] = jb + 1; }
        if (v.z != 0.f) { int p = atomicAdd(&s_cnt, 1); if (p < MAXDEG) s_list[p] = jb + 2; }
        if (v.w != 0.f) { int p = atomicAdd(&s_cnt, 1); if (p < MAXDEG) s_list[p] = jb + 3; }
    }
    __syncthreads();
    int deg = min(s_cnt, MAXDEG);

    float sa1_0 = g_sa1[i];
    float sa1_1 = g_sa1[N_NODES + i];

    // ---- phase 2: leaky scores + max (0 included: non-neighbor entries) ----
    float m0 = 0.f, m1 = 0.f;
    for (int t = tid; t < deg; t += 256) {
        int j = s_list[t];
        float w0 = sa1_0 + g_sa2[j];
        float w1 = sa1_1 + g_sa2[N_NODES + j];
        w0 = (w0 >= 0.f) ? w0 : ALPHA * w0;
        w1 = (w1 >= 0.f) ? w1 : ALPHA * w1;
        s_w0[t] = w0; s_w1[t] = w1;
        m0 = fmaxf(m0, w0); m1 = fmaxf(m1, w1);
    }
    #pragma unroll
    for (int o = 16; o > 0; o >>= 1) {
        m0 = fmaxf(m0, __shfl_down_sync(0xffffffffu, m0, o));
        m1 = fmaxf(m1, __shfl_down_sync(0xffffffffu, m1, o));
    }
    if ((tid & 31) == 0) { s_red[tid >> 5] = m0; s_red[8 + (tid >> 5)] = m1; }
    __syncthreads();
    if (tid == 0) {
        float a = 0.f, b = 0.f;
        for (int w = 0; w < 8; ++w) { a = fmaxf(a, s_red[w]); b = fmaxf(b, s_red[8 + w]); }
        s_bc[0] = a; s_bc[1] = b;
    }
    __syncthreads();
    m0 = s_bc[0]; m1 = s_bc[1];
    float em0 = __expf(-m0), em1 = __expf(-m1);

    // ---- phase 3: exp + sum -> Z ----
    float z0 = 0.f, z1 = 0.f;
    for (int t = tid; t < deg; t += 256) {
        float e0 = __expf(s_w0[t] - m0);
        float e1 = __expf(s_w1[t] - m1);
        s_w0[t] = e0; s_w1[t] = e1;
        z0 += e0; z1 += e1;
    }
    #pragma unroll
    for (int o = 16; o > 0; o >>= 1) {
        z0 += __shfl_down_sync(0xffffffffu, z0, o);
        z1 += __shfl_down_sync(0xffffffffu, z1, o);
    }
    if ((tid & 31) == 0) { s_red[tid >> 5] = z0; s_red[8 + (tid >> 5)] = z1; }
    __syncthreads();
    if (tid == 0) {
        float a = 0.f, b = 0.f;
        for (int w = 0; w < 8; ++w) { a += s_red[w]; b += s_red[8 + w]; }
        a += (float)(N_NODES - deg) * em0;
        b += (float)(N_NODES - deg) * em1;
        s_bc[2] = a; s_bc[3] = b;
    }
    __syncthreads();
    float iz0 = 1.f / s_bc[2];
    float iz1 = 1.f / s_bc[3];

    // ---- phase 4: convert exp -> beta = (e - exp(-m))/Z  (own slots, no hazard) ----
    for (int t = tid; t < deg; t += 256) {
        s_w0[t] = (s_w0[t] - em0) * iz0;
        s_w1[t] = (s_w1[t] - em1) * iz1;
    }
    __syncthreads();

    // ---- phase 5: gather x rows, accumulate g for both heads ----
    int d = tid & 127;
    int half = tid >> 7;
    float g0 = 0.f, g1 = 0.f;
    #pragma unroll 4
    for (int t = half; t < deg; t += 2) {
        float xv = __ldg(&x[(size_t)s_list[t] * F_DIM + d]);
        float b0 = s_w0[t], b1 = s_w1[t];
        g0 = fmaf(b0, xv, g0);
        g1 = fmaf(b1, xv, g1);
    }
    if (half == 1) { s_acc[d] = g0; s_acc[128 + d] = g1; }
    __syncthreads();
    if (half == 0) {
        g0 += s_acc[d];
        g1 += s_acc[128 + d];
        float sx = g_Sx[d];
        g0 = fmaf(em0 * iz0, sx, g0);
        g1 = fmaf(em1 * iz1, sx, g1);
        g_G[(size_t)i * 256 + d]       = g0;
        g_G[(size_t)i * 256 + 128 + d] = g1;
    }
}

// ============================================================
// Kernel 5: out = 0.5*(G @ kernel_flat) + 0.5*(bias0+bias1)
//   G: [8192,256]  kernel_flat: [256,128]  (H,F,D flattening == concat)
// ============================================================
__global__ void __launch_bounds__(256) gemm_kernel(const float* __restrict__ Kw,
                                                   const float* __restrict__ bias,
                                                   float* __restrict__ out) {
    __shared__ float As[32][65];    // [k][row]
    __shared__ float Bs[32][132];   // [k][col]
    int tid = threadIdx.x;
    int tx = tid & 15;              // col group
    int ty = tid >> 4;              // row group
    int row0 = blockIdx.x * 64;

    float acc[4][8];
    #pragma unroll
    for (int u = 0; u < 4; ++u)
        #pragma unroll
        for (int v = 0; v < 8; ++v) acc[u][v] = 0.f;

    for (int kk = 0; kk < 256; kk += 32) {
        // A tile: 64 rows x 32 k
        {
            int r = tid >> 2;
            int c = (tid & 3) * 8;
            const float4* gp = reinterpret_cast<const float4*>(g_G + (size_t)(row0 + r) * 256 + kk + c);
            #pragma unroll
            for (int u = 0; u < 2; ++u) {
                float4 v = gp[u];
                As[c + u * 4 + 0][r] = v.x;
                As[c + u * 4 + 1][r] = v.y;
                As[c + u * 4 + 2][r] = v.z;
                As[c + u * 4 + 3][r] = v.w;
            }
        }
        // B tile: 32 k x 128 cols
        {
            int r = tid >> 3;
            int c = (tid & 7) * 16;
            const float4* kp = reinterpret_cast<const float4*>(Kw + (size_t)(kk + r) * 128 + c);
            #pragma unroll
            for (int u = 0; u < 4; ++u) {
                float4 v = kp[u];
                Bs[r][c + u * 4 + 0] = v.x;
                Bs[r][c + u * 4 + 1] = v.y;
                Bs[r][c + u * 4 + 2] = v.z;
                Bs[r][c + u * 4 + 3] = v.w;
            }
        }
        __syncthreads();
        #pragma unroll
        for (int k = 0; k < 32; ++k) {
            float a[4], b[8];
            #pragma unroll
            for (int u = 0; u < 4; ++u) a[u] = As[k][ty * 4 + u];
            #pragma unroll
            for (int v = 0; v < 8; ++v) b[v] = Bs[k][tx + v * 16];
            #pragma unroll
            for (int u = 0; u < 4; ++u)
                #pragma unroll
                for (int v = 0; v < 8; ++v)
                    acc[u][v] = fmaf(a[u], b[v], acc[u][v]);
        }
        __syncthreads();
    }

    #pragma unroll
    for (int u = 0; u < 4; ++u) {
        int row = row0 + ty * 4 + u;
        #pragma unroll
        for (int v = 0; v < 8; ++v) {
            int col = tx + v * 16;
            size_t o = (size_t)row * 128 + col;
            out[o] = 0.5f * (acc[u][v] + bias[o] + bias[(size_t)N_NODES * 128 + o]);
        }
    }
}

// ============================================================
extern "C" void kernel_launch(void* const* d_in, const int* in_sizes, int n_in,
                              void* d_out, int out_size) {
    const float* x    = (const float*)d_in[0];
    const float* adj  = (const float*)d_in[1];
    const float* Wmap = (const float*)d_in[2];
    const float* a1w  = (const float*)d_in[3];
    const float* a1b  = (const float*)d_in[4];
    const float* a2w  = (const float*)d_in[5];
    const float* a2b  = (const float*)d_in[6];
    const float* kern = (const float*)d_in[7];
    const float* bias = (const float*)d_in[8];
    float* out = (float*)d_out;

    prep_kernel<<<1, 256>>>(Wmap, a1w, a2w);
    colsum_kernel<<<128, 128>>>(x);
    score_kernel<<<1024, 256>>>(x, a1b, a2b);
    gat_main<<<N_NODES, 256>>>(adj, x);
    gemm_kernel<<<128, 256>>>(kern, bias, out);
}